// round 6
// baseline (speedup 1.0000x reference)
#include <cuda_runtime.h>

// CAM_43344809951340: per-sample symmetric tanh outer-product attention.
// out rows l / l+32 of T[i][j]=tanh(av_i av_j s) contracted with Wca/Wcv.
// R6: pack {row l, row l+32} of ONE sample into an f16x2. For column pair
// j=l^m: tanh2(v2*x2) gives both same-half terms, tanh2(v2*swap(x2)) gives
// both cross terms -> 1 SHFL + 1 PRMT + 2 HMUL2 + 2 TANH2 + 2 HFMA2 per
// (m,sample), no SELs, no t-exchange in the dependency chain. Drops the
// symmetry trick: becomes cleanly MUFU-bound (~86k cyc/SM floor) instead of
// latency-exposed across three half-idle pipes.

#define RS 0.35355339059327379f   // sqrt(1/8)
#define S 8

typedef unsigned long long u64;
typedef unsigned int u32;

__device__ int g_cam_counter;

__device__ __forceinline__ u64 ffma2(u64 a, u64 b, u64 c) {
    u64 d; asm("fma.rn.f32x2 %0,%1,%2,%3;" : "=l"(d) : "l"(a), "l"(b), "l"(c));
    return d;
}
__device__ __forceinline__ u64 pack2(float lo, float hi) {
    u64 d; asm("mov.b64 %0,{%1,%2};" : "=l"(d) : "f"(lo), "f"(hi));
    return d;
}
__device__ __forceinline__ float2 unpack2(u64 a) {
    float2 r; asm("mov.b64 {%0,%1},%2;" : "=f"(r.x), "=f"(r.y) : "l"(a));
    return r;
}
__device__ __forceinline__ u32 hmul2(u32 a, u32 b) {
    u32 d; asm("mul.rn.f16x2 %0,%1,%2;" : "=r"(d) : "r"(a), "r"(b));
    return d;
}
__device__ __forceinline__ u32 hfma2(u32 a, u32 b, u32 c) {
    u32 d; asm("fma.rn.f16x2 %0,%1,%2,%3;" : "=r"(d) : "r"(a), "r"(b), "r"(c));
    return d;
}
__device__ __forceinline__ u32 tanh2(u32 a) {
    u32 d; asm("tanh.approx.f16x2 %0,%1;" : "=r"(d) : "r"(a));
    return d;
}
// pack two f32 into f16x2 (first asm source -> HIGH half, so pass (hi, lo))
__device__ __forceinline__ u32 f2h2(float lo, float hi) {
    u32 d; asm("cvt.rn.f16x2.f32 %0,%1,%2;" : "=r"(d) : "f"(hi), "f"(lo));
    return d;
}
// widen f16x2 -> f32x2 (low->low)
__device__ __forceinline__ u64 h2f2(u32 h) {
    u64 d;
    asm("{.reg .f16 h0,h1; .reg .f32 f0,f1;\n\t"
        "mov.b32 {h0,h1},%1;\n\t"
        "cvt.f32.f16 f0,h0; cvt.f32.f16 f1,h1;\n\t"
        "mov.b64 %0,{f0,f1};}" : "=l"(d) : "r"(h));
    return d;
}

__global__ __launch_bounds__(128, 8)
void cam_kernel(const float* __restrict__ f1, const float* __restrict__ f2,
                const float* __restrict__ Wca, const float* __restrict__ Wcv,
                float* __restrict__ out, int B)
{
    // Per-(m,lane) weight pair, f16x2-packed (one LDS.64 per m, amortized S=8):
    //  .x = {Wca[j] lo, Wcv[j+32] hi}   -> same-half terms, rows l / l+32
    //  .y = {Wca[j+32] lo, Wcv[j] hi}   -> cross terms,     rows l / l+32
    // m=0 row covers diagonal + (l,l+32) pair with identical code.
    __shared__ uint2 wq[32][32];

    const int tid = threadIdx.x;
    for (int idx = tid; idx < 32 * 32; idx += blockDim.x) {
        int m = idx >> 5;
        int l2 = idx & 31;
        int j = l2 ^ m;
        uint2 e;
        e.x = f2h2(Wca[j],      Wcv[j + 32]);
        e.y = f2h2(Wca[j + 32], Wcv[j]);
        wq[m][l2] = e;
    }
    __syncthreads();

    const int l = tid & 31;
    const u64 ONE2 = pack2(1.0f, 1.0f);
    const int nbatch = (B + S - 1) / S;

    int batch = 0;
    if (l == 0) batch = atomicAdd(&g_cam_counter, 1);
    batch = __shfl_sync(0xffffffffu, batch, 0);

    while (batch < nbatch) {
        int nextb = 0;
        if (l == 0) nextb = atomicAdd(&g_cam_counter, 1);  // prefetch next id
        nextb = __shfl_sync(0xffffffffu, nextb, 0);

        const int base = batch * S;

        u32 v2[S];     // f16x2 {al, ah} pre-scaled av rows of this lane
        u32 pc[S];     // f16x2 partial accumulators {row l, row l+32}
        u64 a2[S];     // f32x2 master accumulators (residual init)

        #pragma unroll
        for (int k = 0; k < S; k++) {
            int b = base + k;
            bool v = b < B;
            float x0 = v ? f1[b * 32 + l] : 0.0f;
            float y0 = v ? f2[b * 32 + l] : 0.0f;
            a2[k] = pack2(x0, y0);            // residuals: row l, row l+32
            v2[k] = f2h2(x0 * RS, y0 * RS);
            pc[k] = 0u;
        }

        // Rolled m-loop (body ~70 inst stays in L0 I$). m=0 handles diagonal.
        #pragma unroll 1
        for (int m = 0; m < 32; m++) {
            const uint2 w = wq[m][l];
            #pragma unroll
            for (int k = 0; k < S; k++) {
                u32 x2 = __shfl_xor_sync(0xffffffffu, v2[k], m); // {al[j],ah[j]}
                u32 xs = __byte_perm(x2, x2, 0x1032);            // {ah[j],al[j]}
                u32 ts = tanh2(hmul2(v2[k], x2));  // {T[l][j],    T[l+32][j+32]}
                u32 tc = tanh2(hmul2(v2[k], xs));  // {T[l][j+32], T[l+32][j]}
                pc[k] = hfma2(ts, w.x, pc[k]);
                pc[k] = hfma2(tc, w.y, pc[k]);
            }
            if (m == 15) {   // mid-loop flush: 32 f16 terms max per half
                #pragma unroll
                for (int k = 0; k < S; k++) {
                    a2[k] = ffma2(h2f2(pc[k]), ONE2, a2[k]);
                    pc[k] = 0u;
                }
            }
        }

        #pragma unroll
        for (int k = 0; k < S; k++) {
            a2[k] = ffma2(h2f2(pc[k]), ONE2, a2[k]);   // final flush
            float2 r = unpack2(a2[k]);
            int b = base + k;
            if (b < B) {
                out[b * 64 + l]      = 0.1f * fmaxf(r.x, 0.0f);
                out[b * 64 + 32 + l] = 0.1f * fmaxf(r.y, 0.0f);
            }
        }

        batch = nextb;
    }
}

extern "C" void kernel_launch(void* const* d_in, const int* in_sizes, int n_in,
                              void* d_out, int out_size) {
    const float* f1  = (const float*)d_in[0];
    const float* f2  = (const float*)d_in[1];
    const float* Wca = (const float*)d_in[2];
    const float* Wcv = (const float*)d_in[3];
    float* out = (float*)d_out;

    const int B = in_sizes[0] / 32;

    void* ctr = nullptr;
    cudaGetSymbolAddress(&ctr, g_cam_counter);
    cudaMemsetAsync(ctr, 0, sizeof(int));

    // 8 blocks/SM x 148 SMs x 4 warps; atomic work stealing with prefetch.
    cam_kernel<<<1184, 128>>>(f1, f2, Wca, Wcv, out, B);
}

// round 7
// speedup vs baseline: 1.3149x; 1.3149x over previous
#include <cuda_runtime.h>
#include <math.h>

// CAM_43344809951340: per-sample symmetric tanh outer-product attention.
// R7: MUFU is the wall (tanh.approx.f16x2 = 2 MUFU slots; ncu hides the XU
// pipe). Split tanh evaluation across pipes: same-half tanhs + even-m cross
// tanhs on MUFU (tanh2); odd-m cross tanhs via deg-15 odd polynomial in
// packed f32x2 on the FMA pipe. Poly coefficients: runtime Chebyshev-node
// interpolation (DCT at T8 roots, exact basis conversion) by thread 0 of
// each block. Loop interleaves one poly-m and one MUFU-m per iteration.

#define RS 0.35355339059327379f   // sqrt(1/8)
#define S 8
#define P 4

typedef unsigned long long u64;
typedef unsigned int u32;

__device__ int g_cam_counter;

// ---- packed helpers ----
__device__ __forceinline__ u64 ffma2(u64 a, u64 b, u64 c) {
    u64 d; asm("fma.rn.f32x2 %0,%1,%2,%3;" : "=l"(d) : "l"(a), "l"(b), "l"(c));
    return d;
}
__device__ __forceinline__ u64 fmul2(u64 a, u64 b) {
    u64 d; asm("mul.rn.f32x2 %0,%1,%2;" : "=l"(d) : "l"(a), "l"(b));
    return d;
}
__device__ __forceinline__ u64 pack2(float lo, float hi) {
    u64 d; asm("mov.b64 %0,{%1,%2};" : "=l"(d) : "f"(lo), "f"(hi));
    return d;
}
__device__ __forceinline__ float2 unpack2(u64 a) {
    float2 r; asm("mov.b64 {%0,%1},%2;" : "=f"(r.x), "=f"(r.y) : "l"(a));
    return r;
}
__device__ __forceinline__ u32 hmul2(u32 a, u32 b) {
    u32 d; asm("mul.rn.f16x2 %0,%1,%2;" : "=r"(d) : "r"(a), "r"(b));
    return d;
}
__device__ __forceinline__ u32 hfma2(u32 a, u32 b, u32 c) {
    u32 d; asm("fma.rn.f16x2 %0,%1,%2,%3;" : "=r"(d) : "r"(a), "r"(b), "r"(c));
    return d;
}
__device__ __forceinline__ u32 tanh2(u32 a) {
    u32 d; asm("tanh.approx.f16x2 %0,%1;" : "=r"(d) : "r"(a));
    return d;
}
__device__ __forceinline__ u32 hmin2(u32 a, u32 b) {
    u32 d; asm("min.f16x2 %0,%1,%2;" : "=r"(d) : "r"(a), "r"(b));
    return d;
}
__device__ __forceinline__ u32 hmax2(u32 a, u32 b) {
    u32 d; asm("max.f16x2 %0,%1,%2;" : "=r"(d) : "r"(a), "r"(b));
    return d;
}
// pack two f32 into f16x2 (low sample -> low half)
__device__ __forceinline__ u32 f2h2(float lo, float hi) {
    u32 d; asm("cvt.rn.f16x2.f32 %0,%1,%2;" : "=r"(d) : "f"(hi), "f"(lo));
    return d;
}
// widen f16x2 -> f32x2 (low->low)
__device__ __forceinline__ u64 h2f2(u32 h) {
    u64 d;
    asm("{.reg .f16 h0,h1; .reg .f32 f0,f1;\n\t"
        "mov.b32 {h0,h1},%1;\n\t"
        "cvt.f32.f16 f0,h0; cvt.f32.f16 f1,h1;\n\t"
        "mov.b64 %0,{f0,f1};}" : "=l"(d) : "r"(h));
    return d;
}

#define H2_P25 0x41004100u   // {+2.5h, +2.5h}
#define H2_M25 0xC100C100u   // {-2.5h, -2.5h}

__global__ __launch_bounds__(128, 6)
void cam_kernel(const float* __restrict__ f1, const float* __restrict__ f2,
                const float* __restrict__ Wca, const float* __restrict__ Wcv,
                float* __restrict__ out, int B)
{
    // f16x2-packed weight table (LDS.128 per m per unit):
    //  .x={Wca[j]}x2 (same, row l)  .y={Wcv[j+32]}x2 (same, row l+32)
    //  .z={Wca[j+32]}x2 (cross, row l)  .w={Wcv[j]}x2 (cross, row l+32)
    __shared__ uint4 wq[31][32];
    __shared__ float csh[8];   // monomial coeffs of tanh(x)/x in zh

    const int tid = threadIdx.x;
    for (int idx = tid; idx < 31 * 32; idx += blockDim.x) {
        int m = (idx >> 5) + 1;
        int l2 = idx & 31;
        int j = l2 ^ m;
        uint4 e;
        e.x = f2h2(Wca[j],      Wca[j]);
        e.y = f2h2(Wcv[j + 32], Wcv[j + 32]);
        e.z = f2h2(Wca[j + 32], Wca[j + 32]);
        e.w = f2h2(Wcv[j],      Wcv[j]);
        wq[m - 1][l2] = e;
    }

    // Thread 0: deg-15 odd interpolant tanh(x) ~ x*P(zh), zh = x^2*(2/6.25)-1,
    // via DCT at the 8 roots of T8 + exact Chebyshev->monomial conversion.
    if (tid == 0) {
        float g[8], th[8], c[8];
        const float Wiv = 6.25f;
        #pragma unroll 1
        for (int i = 0; i < 8; i++) {
            float theta = (2.0f * i + 1.0f) * 0.19634954084936207f; // pi/16
            float wh = cosf(theta);
            float wi = 0.5f * Wiv * (wh + 1.0f);
            float xi = sqrtf(wi);
            g[i] = tanhf(xi) / xi;
            th[i] = theta;
        }
        #pragma unroll 1
        for (int k = 0; k < 8; k++) {
            float s = 0.0f;
            for (int i = 0; i < 8; i++) s += g[i] * cosf((float)k * th[i]);
            c[k] = s * ((k == 0) ? 0.125f : 0.25f);
        }
        csh[0] = c[0] - c[2] + c[4] - c[6];
        csh[1] = c[1] - 3.f*c[3] + 5.f*c[5] - 7.f*c[7];
        csh[2] = 2.f*c[2] - 8.f*c[4] + 18.f*c[6];
        csh[3] = 4.f*c[3] - 20.f*c[5] + 56.f*c[7];
        csh[4] = 8.f*c[4] - 48.f*c[6];
        csh[5] = 16.f*c[5] - 112.f*c[7];
        csh[6] = 32.f*c[6];
        csh[7] = 64.f*c[7];
    }
    __syncthreads();

    u64 A[8];
    #pragma unroll
    for (int j = 0; j < 8; j++) A[j] = pack2(csh[j], csh[j]);
    const u64 K2  = pack2(0.32f, 0.32f);    // 2/6.25
    const u64 KM1 = pack2(-1.0f, -1.0f);
    const u64 ONE2 = pack2(1.0f, 1.0f);

    const int l = tid & 31;
    const u64 wdd0 = pack2(Wca[l], Wca[l]);
    const u64 wdd1 = pack2(Wcv[l + 32], Wcv[l + 32]);
    const u64 wmm0 = pack2(Wca[l + 32], Wca[l + 32]);
    const u64 wmm1 = pack2(Wcv[l], Wcv[l]);

    const int nbatch = (B + S - 1) / S;

    int batch = 0;
    if (l == 0) batch = atomicAdd(&g_cam_counter, 1);
    batch = __shfl_sync(0xffffffffu, batch, 0);

    while (batch < nbatch) {
        int nextb = 0;
        if (l == 0) nextb = atomicAdd(&g_cam_counter, 1);
        nextb = __shfl_sync(0xffffffffu, nextb, 0);

        const int base = batch * S;

        u32 al2[P], ah2[P];   // f16x2 pre-scaled av halves (2 samples each)
        u64 a0[P], a1[P];     // f32x2 master accumulators
        u32 p0[P], p1[P];     // f16x2 partial accumulators

        #pragma unroll
        for (int p = 0; p < P; p++) {
            int b0 = base + 2 * p, b1 = b0 + 1;
            bool v0 = b0 < B, v1 = b1 < B;
            float x0 = v0 ? f1[b0 * 32 + l] : 0.0f;
            float x1 = v1 ? f1[b1 * 32 + l] : 0.0f;
            float y0 = v0 ? f2[b0 * 32 + l] : 0.0f;
            float y1 = v1 ? f2[b1 * 32 + l] : 0.0f;
            a0[p] = pack2(x0, x1);
            a1[p] = pack2(y0, y1);
            al2[p] = f2h2(x0 * RS, x1 * RS);
            ah2[p] = f2h2(y0 * RS, y1 * RS);
            p0[p] = 0u; p1[p] = 0u;
        }

        // Diagonal + (l, l+32) pair (MUFU, f32x2 accumulate)
        #pragma unroll
        for (int p = 0; p < P; p++) {
            a0[p] = ffma2(h2f2(tanh2(hmul2(al2[p], al2[p]))), wdd0, a0[p]);
            a1[p] = ffma2(h2f2(tanh2(hmul2(ah2[p], ah2[p]))), wdd1, a1[p]);
            u64 tmf = h2f2(tanh2(hmul2(al2[p], ah2[p])));
            a0[p] = ffma2(tmf, wmm0, a0[p]);
            a1[p] = ffma2(tmf, wmm1, a1[p]);
        }

        // Same-half terms: MUFU always. Cross terms: odd m -> poly (FMA pipe),
        // even m -> MUFU. One poly-m + one mufu-m per iteration (pipe mixing).
        #pragma unroll 1
        for (int mo = 1; mo < 32; mo += 2) {
            // ---------- m = mo (odd): same-half MUFU + cross POLY ----------
            {
                const int m = mo;
                const bool lo = l < (l ^ m);
                const uint4 w = wq[m - 1][l];
                #pragma unroll
                for (int p = 0; p < P; p++) {
                    // same-half (MUFU)
                    u32 send2 = lo ? ah2[p] : al2[p];
                    u32 x2 = __shfl_xor_sync(0xffffffffu, send2, m);
                    u32 sc2 = lo ? al2[p] : ah2[p];
                    u32 t2 = tanh2(hmul2(sc2, x2));
                    u32 to2 = __shfl_xor_sync(0xffffffffu, t2, m);
                    u32 tl2 = lo ? t2 : to2;
                    u32 th2 = lo ? to2 : t2;
                    p0[p] = hfma2(tl2, w.x, p0[p]);
                    p1[p] = hfma2(th2, w.y, p1[p]);
                    // cross (poly on FMA pipe)
                    u32 xh2 = __shfl_xor_sync(0xffffffffu, ah2[p], m);
                    u32 arg = hmul2(al2[p], xh2);
                    arg = hmin2(hmax2(arg, H2_M25), H2_P25);
                    u64 a = h2f2(arg);
                    u64 s = fmul2(a, a);
                    u64 zh = ffma2(s, K2, KM1);
                    u64 q = A[7];
                    q = ffma2(q, zh, A[6]);
                    q = ffma2(q, zh, A[5]);
                    q = ffma2(q, zh, A[4]);
                    q = ffma2(q, zh, A[3]);
                    q = ffma2(q, zh, A[2]);
                    q = ffma2(q, zh, A[1]);
                    q = ffma2(q, zh, A[0]);
                    u64 tf = fmul2(a, q);
                    float2 tp = unpack2(tf);
                    u32 ta2 = f2h2(tp.x, tp.y);
                    u32 tb2 = __shfl_xor_sync(0xffffffffu, ta2, m);
                    p0[p] = hfma2(ta2, w.z, p0[p]);
                    p1[p] = hfma2(tb2, w.w, p1[p]);
                }
            }
            // ---------- m = mo+1 (even): full MUFU unit ----------
            if (mo < 31) {
                const int m = mo + 1;
                const bool lo = l < (l ^ m);
                const uint4 w = wq[m - 1][l];
                #pragma unroll
                for (int p = 0; p < P; p++) {
                    u32 send2 = lo ? ah2[p] : al2[p];
                    u32 x2 = __shfl_xor_sync(0xffffffffu, send2, m);
                    u32 sc2 = lo ? al2[p] : ah2[p];
                    u32 t2 = tanh2(hmul2(sc2, x2));
                    u32 to2 = __shfl_xor_sync(0xffffffffu, t2, m);
                    u32 tl2 = lo ? t2 : to2;
                    u32 th2 = lo ? to2 : t2;
                    p0[p] = hfma2(tl2, w.x, p0[p]);
                    p1[p] = hfma2(th2, w.y, p1[p]);
                    u32 xh2 = __shfl_xor_sync(0xffffffffu, ah2[p], m);
                    u32 ta2 = tanh2(hmul2(al2[p], xh2));
                    u32 tb2 = __shfl_xor_sync(0xffffffffu, ta2, m);
                    p0[p] = hfma2(ta2, w.z, p0[p]);
                    p1[p] = hfma2(tb2, w.w, p1[p]);
                }
            }
            if (mo == 15) {   // mid-loop flush of f16 partials into f32x2
                #pragma unroll
                for (int p = 0; p < P; p++) {
                    a0[p] = ffma2(h2f2(p0[p]), ONE2, a0[p]);
                    a1[p] = ffma2(h2f2(p1[p]), ONE2, a1[p]);
                    p0[p] = 0u; p1[p] = 0u;
                }
            }
        }

        #pragma unroll
        for (int p = 0; p < P; p++) {
            a0[p] = ffma2(h2f2(p0[p]), ONE2, a0[p]);
            a1[p] = ffma2(h2f2(p1[p]), ONE2, a1[p]);
            float2 r0 = unpack2(a0[p]);
            float2 r1 = unpack2(a1[p]);
            int b0 = base + 2 * p, b1 = b0 + 1;
            if (b0 < B) {
                out[b0 * 64 + l]      = 0.1f * fmaxf(r0.x, 0.0f);
                out[b0 * 64 + 32 + l] = 0.1f * fmaxf(r1.x, 0.0f);
            }
            if (b1 < B) {
                out[b1 * 64 + l]      = 0.1f * fmaxf(r0.y, 0.0f);
                out[b1 * 64 + 32 + l] = 0.1f * fmaxf(r1.y, 0.0f);
            }
        }

        batch = nextb;
    }
}

extern "C" void kernel_launch(void* const* d_in, const int* in_sizes, int n_in,
                              void* d_out, int out_size) {
    const float* f1  = (const float*)d_in[0];
    const float* f2  = (const float*)d_in[1];
    const float* Wca = (const float*)d_in[2];
    const float* Wcv = (const float*)d_in[3];
    float* out = (float*)d_out;

    const int B = in_sizes[0] / 32;

    void* ctr = nullptr;
    cudaGetSymbolAddress(&ctr, g_cam_counter);
    cudaMemsetAsync(ctr, 0, sizeof(int));

    // 6 blocks/SM x 148 SMs x 4 warps; atomic work stealing with prefetch.
    cam_kernel<<<888, 128>>>(f1, f2, Wca, Wcv, out, B);
}

// round 8
// speedup vs baseline: 1.3159x; 1.0008x over previous
#include <cuda_runtime.h>
#include <math.h>

// CAM_43344809951340: per-sample symmetric tanh outer-product attention.
// R7: MUFU is the wall (tanh.approx.f16x2 = 2 MUFU slots; ncu hides the XU
// pipe). Split tanh evaluation across pipes: same-half tanhs + even-m cross
// tanhs on MUFU (tanh2); odd-m cross tanhs via deg-15 odd polynomial in
// packed f32x2 on the FMA pipe. Poly coefficients: runtime Chebyshev-node
// interpolation (DCT at T8 roots, exact basis conversion) by thread 0 of
// each block. Loop interleaves one poly-m and one MUFU-m per iteration.

#define RS 0.35355339059327379f   // sqrt(1/8)
#define S 8
#define P 4

typedef unsigned long long u64;
typedef unsigned int u32;

__device__ int g_cam_counter;

// ---- packed helpers ----
__device__ __forceinline__ u64 ffma2(u64 a, u64 b, u64 c) {
    u64 d; asm("fma.rn.f32x2 %0,%1,%2,%3;" : "=l"(d) : "l"(a), "l"(b), "l"(c));
    return d;
}
__device__ __forceinline__ u64 fmul2(u64 a, u64 b) {
    u64 d; asm("mul.rn.f32x2 %0,%1,%2;" : "=l"(d) : "l"(a), "l"(b));
    return d;
}
__device__ __forceinline__ u64 pack2(float lo, float hi) {
    u64 d; asm("mov.b64 %0,{%1,%2};" : "=l"(d) : "f"(lo), "f"(hi));
    return d;
}
__device__ __forceinline__ float2 unpack2(u64 a) {
    float2 r; asm("mov.b64 {%0,%1},%2;" : "=f"(r.x), "=f"(r.y) : "l"(a));
    return r;
}
__device__ __forceinline__ u32 hmul2(u32 a, u32 b) {
    u32 d; asm("mul.rn.f16x2 %0,%1,%2;" : "=r"(d) : "r"(a), "r"(b));
    return d;
}
__device__ __forceinline__ u32 hfma2(u32 a, u32 b, u32 c) {
    u32 d; asm("fma.rn.f16x2 %0,%1,%2,%3;" : "=r"(d) : "r"(a), "r"(b), "r"(c));
    return d;
}
__device__ __forceinline__ u32 tanh2(u32 a) {
    u32 d; asm("tanh.approx.f16x2 %0,%1;" : "=r"(d) : "r"(a));
    return d;
}
__device__ __forceinline__ u32 hmin2(u32 a, u32 b) {
    u32 d; asm("min.f16x2 %0,%1,%2;" : "=r"(d) : "r"(a), "r"(b));
    return d;
}
__device__ __forceinline__ u32 hmax2(u32 a, u32 b) {
    u32 d; asm("max.f16x2 %0,%1,%2;" : "=r"(d) : "r"(a), "r"(b));
    return d;
}
// pack two f32 into f16x2 (low sample -> low half)
__device__ __forceinline__ u32 f2h2(float lo, float hi) {
    u32 d; asm("cvt.rn.f16x2.f32 %0,%1,%2;" : "=r"(d) : "f"(hi), "f"(lo));
    return d;
}
// widen f16x2 -> f32x2 (low->low)
__device__ __forceinline__ u64 h2f2(u32 h) {
    u64 d;
    asm("{.reg .f16 h0,h1; .reg .f32 f0,f1;\n\t"
        "mov.b32 {h0,h1},%1;\n\t"
        "cvt.f32.f16 f0,h0; cvt.f32.f16 f1,h1;\n\t"
        "mov.b64 %0,{f0,f1};}" : "=l"(d) : "r"(h));
    return d;
}

#define H2_P25 0x41004100u   // {+2.5h, +2.5h}
#define H2_M25 0xC100C100u   // {-2.5h, -2.5h}

__global__ __launch_bounds__(128, 6)
void cam_kernel(const float* __restrict__ f1, const float* __restrict__ f2,
                const float* __restrict__ Wca, const float* __restrict__ Wcv,
                float* __restrict__ out, int B)
{
    // f16x2-packed weight table (LDS.128 per m per unit):
    //  .x={Wca[j]}x2 (same, row l)  .y={Wcv[j+32]}x2 (same, row l+32)
    //  .z={Wca[j+32]}x2 (cross, row l)  .w={Wcv[j]}x2 (cross, row l+32)
    __shared__ uint4 wq[31][32];
    __shared__ float csh[8];   // monomial coeffs of tanh(x)/x in zh

    const int tid = threadIdx.x;
    for (int idx = tid; idx < 31 * 32; idx += blockDim.x) {
        int m = (idx >> 5) + 1;
        int l2 = idx & 31;
        int j = l2 ^ m;
        uint4 e;
        e.x = f2h2(Wca[j],      Wca[j]);
        e.y = f2h2(Wcv[j + 32], Wcv[j + 32]);
        e.z = f2h2(Wca[j + 32], Wca[j + 32]);
        e.w = f2h2(Wcv[j],      Wcv[j]);
        wq[m - 1][l2] = e;
    }

    // Thread 0: deg-15 odd interpolant tanh(x) ~ x*P(zh), zh = x^2*(2/6.25)-1,
    // via DCT at the 8 roots of T8 + exact Chebyshev->monomial conversion.
    if (tid == 0) {
        float g[8], th[8], c[8];
        const float Wiv = 6.25f;
        #pragma unroll 1
        for (int i = 0; i < 8; i++) {
            float theta = (2.0f * i + 1.0f) * 0.19634954084936207f; // pi/16
            float wh = cosf(theta);
            float wi = 0.5f * Wiv * (wh + 1.0f);
            float xi = sqrtf(wi);
            g[i] = tanhf(xi) / xi;
            th[i] = theta;
        }
        #pragma unroll 1
        for (int k = 0; k < 8; k++) {
            float s = 0.0f;
            for (int i = 0; i < 8; i++) s += g[i] * cosf((float)k * th[i]);
            c[k] = s * ((k == 0) ? 0.125f : 0.25f);
        }
        csh[0] = c[0] - c[2] + c[4] - c[6];
        csh[1] = c[1] - 3.f*c[3] + 5.f*c[5] - 7.f*c[7];
        csh[2] = 2.f*c[2] - 8.f*c[4] + 18.f*c[6];
        csh[3] = 4.f*c[3] - 20.f*c[5] + 56.f*c[7];
        csh[4] = 8.f*c[4] - 48.f*c[6];
        csh[5] = 16.f*c[5] - 112.f*c[7];
        csh[6] = 32.f*c[6];
        csh[7] = 64.f*c[7];
    }
    __syncthreads();

    u64 A[8];
    #pragma unroll
    for (int j = 0; j < 8; j++) A[j] = pack2(csh[j], csh[j]);
    const u64 K2  = pack2(0.32f, 0.32f);    // 2/6.25
    const u64 KM1 = pack2(-1.0f, -1.0f);
    const u64 ONE2 = pack2(1.0f, 1.0f);

    const int l = tid & 31;
    const u64 wdd0 = pack2(Wca[l], Wca[l]);
    const u64 wdd1 = pack2(Wcv[l + 32], Wcv[l + 32]);
    const u64 wmm0 = pack2(Wca[l + 32], Wca[l + 32]);
    const u64 wmm1 = pack2(Wcv[l], Wcv[l]);

    const int nbatch = (B + S - 1) / S;

    int batch = 0;
    if (l == 0) batch = atomicAdd(&g_cam_counter, 1);
    batch = __shfl_sync(0xffffffffu, batch, 0);

    while (batch < nbatch) {
        int nextb = 0;
        if (l == 0) nextb = atomicAdd(&g_cam_counter, 1);
        nextb = __shfl_sync(0xffffffffu, nextb, 0);

        const int base = batch * S;

        u32 al2[P], ah2[P];   // f16x2 pre-scaled av halves (2 samples each)
        u64 a0[P], a1[P];     // f32x2 master accumulators
        u32 p0[P], p1[P];     // f16x2 partial accumulators

        #pragma unroll
        for (int p = 0; p < P; p++) {
            int b0 = base + 2 * p, b1 = b0 + 1;
            bool v0 = b0 < B, v1 = b1 < B;
            float x0 = v0 ? f1[b0 * 32 + l] : 0.0f;
            float x1 = v1 ? f1[b1 * 32 + l] : 0.0f;
            float y0 = v0 ? f2[b0 * 32 + l] : 0.0f;
            float y1 = v1 ? f2[b1 * 32 + l] : 0.0f;
            a0[p] = pack2(x0, x1);
            a1[p] = pack2(y0, y1);
            al2[p] = f2h2(x0 * RS, x1 * RS);
            ah2[p] = f2h2(y0 * RS, y1 * RS);
            p0[p] = 0u; p1[p] = 0u;
        }

        // Diagonal + (l, l+32) pair (MUFU, f32x2 accumulate)
        #pragma unroll
        for (int p = 0; p < P; p++) {
            a0[p] = ffma2(h2f2(tanh2(hmul2(al2[p], al2[p]))), wdd0, a0[p]);
            a1[p] = ffma2(h2f2(tanh2(hmul2(ah2[p], ah2[p]))), wdd1, a1[p]);
            u64 tmf = h2f2(tanh2(hmul2(al2[p], ah2[p])));
            a0[p] = ffma2(tmf, wmm0, a0[p]);
            a1[p] = ffma2(tmf, wmm1, a1[p]);
        }

        // Same-half terms: MUFU always. Cross terms: odd m -> poly (FMA pipe),
        // even m -> MUFU. One poly-m + one mufu-m per iteration (pipe mixing).
        #pragma unroll 1
        for (int mo = 1; mo < 32; mo += 2) {
            // ---------- m = mo (odd): same-half MUFU + cross POLY ----------
            {
                const int m = mo;
                const bool lo = l < (l ^ m);
                const uint4 w = wq[m - 1][l];
                #pragma unroll
                for (int p = 0; p < P; p++) {
                    // same-half (MUFU)
                    u32 send2 = lo ? ah2[p] : al2[p];
                    u32 x2 = __shfl_xor_sync(0xffffffffu, send2, m);
                    u32 sc2 = lo ? al2[p] : ah2[p];
                    u32 t2 = tanh2(hmul2(sc2, x2));
                    u32 to2 = __shfl_xor_sync(0xffffffffu, t2, m);
                    u32 tl2 = lo ? t2 : to2;
                    u32 th2 = lo ? to2 : t2;
                    p0[p] = hfma2(tl2, w.x, p0[p]);
                    p1[p] = hfma2(th2, w.y, p1[p]);
                    // cross (poly on FMA pipe)
                    u32 xh2 = __shfl_xor_sync(0xffffffffu, ah2[p], m);
                    u32 arg = hmul2(al2[p], xh2);
                    arg = hmin2(hmax2(arg, H2_M25), H2_P25);
                    u64 a = h2f2(arg);
                    u64 s = fmul2(a, a);
                    u64 zh = ffma2(s, K2, KM1);
                    u64 q = A[7];
                    q = ffma2(q, zh, A[6]);
                    q = ffma2(q, zh, A[5]);
                    q = ffma2(q, zh, A[4]);
                    q = ffma2(q, zh, A[3]);
                    q = ffma2(q, zh, A[2]);
                    q = ffma2(q, zh, A[1]);
                    q = ffma2(q, zh, A[0]);
                    u64 tf = fmul2(a, q);
                    float2 tp = unpack2(tf);
                    u32 ta2 = f2h2(tp.x, tp.y);
                    u32 tb2 = __shfl_xor_sync(0xffffffffu, ta2, m);
                    p0[p] = hfma2(ta2, w.z, p0[p]);
                    p1[p] = hfma2(tb2, w.w, p1[p]);
                }
            }
            // ---------- m = mo+1 (even): full MUFU unit ----------
            if (mo < 31) {
                const int m = mo + 1;
                const bool lo = l < (l ^ m);
                const uint4 w = wq[m - 1][l];
                #pragma unroll
                for (int p = 0; p < P; p++) {
                    u32 send2 = lo ? ah2[p] : al2[p];
                    u32 x2 = __shfl_xor_sync(0xffffffffu, send2, m);
                    u32 sc2 = lo ? al2[p] : ah2[p];
                    u32 t2 = tanh2(hmul2(sc2, x2));
                    u32 to2 = __shfl_xor_sync(0xffffffffu, t2, m);
                    u32 tl2 = lo ? t2 : to2;
                    u32 th2 = lo ? to2 : t2;
                    p0[p] = hfma2(tl2, w.x, p0[p]);
                    p1[p] = hfma2(th2, w.y, p1[p]);
                    u32 xh2 = __shfl_xor_sync(0xffffffffu, ah2[p], m);
                    u32 ta2 = tanh2(hmul2(al2[p], xh2));
                    u32 tb2 = __shfl_xor_sync(0xffffffffu, ta2, m);
                    p0[p] = hfma2(ta2, w.z, p0[p]);
                    p1[p] = hfma2(tb2, w.w, p1[p]);
                }
            }
            if (mo == 15) {   // mid-loop flush of f16 partials into f32x2
                #pragma unroll
                for (int p = 0; p < P; p++) {
                    a0[p] = ffma2(h2f2(p0[p]), ONE2, a0[p]);
                    a1[p] = ffma2(h2f2(p1[p]), ONE2, a1[p]);
                    p0[p] = 0u; p1[p] = 0u;
                }
            }
        }

        #pragma unroll
        for (int p = 0; p < P; p++) {
            a0[p] = ffma2(h2f2(p0[p]), ONE2, a0[p]);
            a1[p] = ffma2(h2f2(p1[p]), ONE2, a1[p]);
            float2 r0 = unpack2(a0[p]);
            float2 r1 = unpack2(a1[p]);
            int b0 = base + 2 * p, b1 = b0 + 1;
            if (b0 < B) {
                out[b0 * 64 + l]      = 0.1f * fmaxf(r0.x, 0.0f);
                out[b0 * 64 + 32 + l] = 0.1f * fmaxf(r1.x, 0.0f);
            }
            if (b1 < B) {
                out[b1 * 64 + l]      = 0.1f * fmaxf(r0.y, 0.0f);
                out[b1 * 64 + 32 + l] = 0.1f * fmaxf(r1.y, 0.0f);
            }
        }

        batch = nextb;
    }
}

extern "C" void kernel_launch(void* const* d_in, const int* in_sizes, int n_in,
                              void* d_out, int out_size) {
    const float* f1  = (const float*)d_in[0];
    const float* f2  = (const float*)d_in[1];
    const float* Wca = (const float*)d_in[2];
    const float* Wcv = (const float*)d_in[3];
    float* out = (float*)d_out;

    const int B = in_sizes[0] / 32;

    void* ctr = nullptr;
    cudaGetSymbolAddress(&ctr, g_cam_counter);
    cudaMemsetAsync(ctr, 0, sizeof(int));

    // 6 blocks/SM x 148 SMs x 4 warps; atomic work stealing with prefetch.
    cam_kernel<<<888, 128>>>(f1, f2, Wca, Wcv, out, B);
}

// round 9
// speedup vs baseline: 2.2430x; 1.7045x over previous
#include <cuda_runtime.h>
#include <math.h>

// CAM_43344809951340 — factored-moment formulation.
// out_a[i] = 0.1*relu( sum_j tanh(u_i v_j) Wca_j + u_i/RS ),  u,v = av*RS.
// tanh(x) ~ x * Q(x^2) = sum_k q_k x^(2k+1)  (deg-19 odd, fit |x|<=2.5313)
//  => sum_j tanh(u v_j) W_j = sum_k q_k u^(2k+1) M_k,  M_k = sum_j v_j^(2k+1) W_j.
// Per sample: 64*(2K FMAs) moments + 64 Horner outputs. No MUFU, all f32 FMA.
// Samples with max|z| > 4.5 (poly out of range, ~4e-4 of samples) are flagged
// and re-solved exactly by a fixup kernel (tanh.approx.f32) that overwrites
// their output rows.

#define RS   0.35355339059327379f   // sqrt(1/8)
#define IRS  2.8284271247461903f    // 1/RS
#define KP   10                     // poly terms (degree 19 odd)
#define VMAX 1.5909902576697319f    // 4.5 * RS : flag threshold on scaled v
#define FLAG_CAP 200000

typedef unsigned int u32;

struct Poly { float q[KP]; };

__device__ int g_ctr[2];            // [0] batch counter, [1] flag count
__device__ int g_flag_ids[FLAG_CAP];

__device__ __forceinline__ float tanhfast(float x) {
    float y; asm("tanh.approx.f32 %0, %1;" : "=f"(y) : "f"(x));
    return y;
}

// ---------------- kernel 1: factored-moment main path ----------------
__global__ __launch_bounds__(128, 6)
void cam_poly_kernel(const float* __restrict__ f1, const float* __restrict__ f2,
                     const float* __restrict__ Wca, const float* __restrict__ Wcv,
                     float* __restrict__ out, int B, Poly pc)
{
    __shared__ float  rows[4][32 * 65];   // per-warp: 32 samples x 64 (stride 65)
    __shared__ float2 wsh[64];            // {Wca[j], Wcv[j]}

    const int tid = threadIdx.x;
    const int wrp = tid >> 5;
    const int l   = tid & 31;
    float* R = rows[wrp];

    if (tid < 64) wsh[tid] = make_float2(Wca[tid], Wcv[tid]);
    __syncthreads();

    float q[KP];
    #pragma unroll
    for (int k = 0; k < KP; k++) q[k] = 0.1f * pc.q[k];
    const float r01 = 0.1f * IRS;         // folded residual: 0.1 * u / RS

    const int nbatch = (B + 31) >> 5;

    int batch = 0;
    if (l == 0) batch = atomicAdd(&g_ctr[0], 1);
    batch = __shfl_sync(0xffffffffu, batch, 0);

    while (batch < nbatch) {
        int nextb = 0;
        if (l == 0) nextb = atomicAdd(&g_ctr[0], 1);   // prefetch next id
        nextb = __shfl_sync(0xffffffffu, nextb, 0);

        const int base = batch << 5;

        // ---- stage: coalesced gmem -> smem, pre-scaled by RS ----
        #pragma unroll 4
        for (int c = 0; c < 32; c++) {
            int b = base + c;
            bool v = b < B;
            float x = v ? f1[b * 32 + l] : 0.0f;
            float y = v ? f2[b * 32 + l] : 0.0f;
            R[c * 65 + l]      = x * RS;
            R[c * 65 + 32 + l] = y * RS;
        }
        __syncwarp();

        // ---- phase 1: moments M_k = sum_j v_j^(2k+1) * W_j (lane = sample) ----
        float Ma[KP], Mv[KP];
        #pragma unroll
        for (int k = 0; k < KP; k++) { Ma[k] = 0.0f; Mv[k] = 0.0f; }
        float mx = 0.0f;

        const float* myrow = &R[l * 65];
        #pragma unroll 8
        for (int j = 0; j < 64; j++) {
            float v = myrow[j];
            float2 w = wsh[j];
            mx = fmaxf(mx, fabsf(v));
            float w2 = v * v;
            float p = v;
            #pragma unroll
            for (int k = 0; k < KP; k++) {
                Ma[k] = fmaf(p, w.x, Ma[k]);
                Mv[k] = fmaf(p, w.y, Mv[k]);
                if (k < KP - 1) p *= w2;
            }
        }

        // fold coefficients (incl. 0.1 scale) into moments
        #pragma unroll
        for (int k = 0; k < KP; k++) { Ma[k] *= q[k]; Mv[k] *= q[k]; }

        // ---- phase 2: Horner per output, overwrite row in place ----
        #pragma unroll 8
        for (int i = 0; i < 32; i++) {
            float u = myrow[i];
            float w2 = u * u;
            float A = Ma[KP - 1];
            #pragma unroll
            for (int k = KP - 2; k >= 0; k--) A = fmaf(A, w2, Ma[k]);
            A += r01;
            ((float*)myrow)[i] = fmaxf(u * A, 0.0f);
        }
        #pragma unroll 8
        for (int i = 32; i < 64; i++) {
            float u = myrow[i];
            float w2 = u * u;
            float A = Mv[KP - 1];
            #pragma unroll
            for (int k = KP - 2; k >= 0; k--) A = fmaf(A, w2, Mv[k]);
            A += r01;
            ((float*)myrow)[i] = fmaxf(u * A, 0.0f);
        }

        // flag out-of-range samples for the exact fixup kernel
        if (mx > VMAX && (base + l) < B) {
            int slot = atomicAdd(&g_ctr[1], 1);
            if (slot < FLAG_CAP) g_flag_ids[slot] = base + l;
        }
        __syncwarp();

        // ---- flush: coalesced smem -> gmem ----
        #pragma unroll 4
        for (int c = 0; c < 32; c++) {
            int b = base + c;
            if (b < B) {
                out[b * 64 + l]      = R[c * 65 + l];
                out[b * 64 + 32 + l] = R[c * 65 + 32 + l];
            }
        }
        __syncwarp();

        batch = nextb;
    }
}

// ---------------- kernel 2: exact fixup for flagged samples ----------------
__global__ __launch_bounds__(128)
void cam_fix_kernel(const float* __restrict__ f1, const float* __restrict__ f2,
                    const float* __restrict__ Wca, const float* __restrict__ Wcv,
                    float* __restrict__ out, int B)
{
    int nflag = g_ctr[1];
    if (nflag > FLAG_CAP) nflag = FLAG_CAP;
    const int l = threadIdx.x & 31;
    const int wid = (blockIdx.x * blockDim.x + threadIdx.x) >> 5;
    const int nw = (gridDim.x * blockDim.x) >> 5;

    const float wca1 = Wca[l], wca2 = Wca[l + 32];
    const float wcv1 = Wcv[l], wcv2 = Wcv[l + 32];

    for (int t = wid; t < nflag; t += nw) {
        int b = g_flag_ids[t];
        float z1 = f1[b * 32 + l];     // av[l]
        float z2 = f2[b * 32 + l];     // av[l+32]
        float acc_a = z1, acc_v = z2;
        #pragma unroll 4
        for (int j = 0; j < 32; j++) {
            float a1 = __shfl_sync(0xffffffffu, z1, j) * 0.125f;  // av[j]*s
            float a2 = __shfl_sync(0xffffffffu, z2, j) * 0.125f;  // av[j+32]*s
            float w1 = __shfl_sync(0xffffffffu, wca1, j);  // Wca[j]
            float w2 = __shfl_sync(0xffffffffu, wca2, j);  // Wca[j+32]
            float w3 = __shfl_sync(0xffffffffu, wcv1, j);  // Wcv[j]
            float w4 = __shfl_sync(0xffffffffu, wcv2, j);  // Wcv[j+32]
            acc_a = fmaf(tanhfast(z1 * a1), w1, acc_a);
            acc_a = fmaf(tanhfast(z1 * a2), w2, acc_a);
            acc_v = fmaf(tanhfast(z2 * a1), w3, acc_v);
            acc_v = fmaf(tanhfast(z2 * a2), w4, acc_v);
        }
        out[b * 64 + l]      = 0.1f * fmaxf(acc_a, 0.0f);
        out[b * 64 + 32 + l] = 0.1f * fmaxf(acc_v, 0.0f);
    }
}

// ---------------- host: deg-19 odd Chebyshev fit of tanh, double precision ----
static Poly make_tanh_poly(void)
{
    const int K = KP;
    const double W = 2.53125 * 2.53125;   // x in [0, 2.53125], w = x^2 in [0, W]
    double g[KP], th[KP], c[KP];
    for (int i = 0; i < K; i++) {
        th[i] = M_PI * (2.0 * i + 1.0) / (2.0 * K);
        double zh = cos(th[i]);
        double w = 0.5 * W * (zh + 1.0);
        double x = sqrt(w);
        g[i] = tanh(x) / x;               // nodes are interior: x > 0
    }
    for (int k = 0; k < K; k++) {
        double s = 0.0;
        for (int i = 0; i < K; i++) s += g[i] * cos(k * th[i]);
        c[k] = s * ((k == 0) ? 1.0 : 2.0) / K;
    }
    // Chebyshev(zh) -> monomial(zh)
    double d[KP + 1] = {0}, tp[KP + 1] = {0}, tc[KP + 1] = {0}, tn[KP + 1];
    tp[0] = 1.0;                 // T0
    tc[1] = 1.0;                 // T1
    d[0] += c[0];
    d[1] += c[1];
    for (int k = 2; k < K; k++) {
        for (int m = 0; m <= K; m++) tn[m] = -tp[m];
        for (int m = K; m >= 1; m--) tn[m] += 2.0 * tc[m - 1];
        for (int m = 0; m <= K; m++) { tp[m] = tc[m]; tc[m] = tn[m]; d[m] += c[k] * tc[m]; }
    }
    // zh = alpha*w - 1 -> monomials in raw w
    double alpha = 2.0 / W;
    double qd[KP] = {0};
    for (int m = 0; m < K; m++) {
        double binom = 1.0;
        for (int k = 0; k <= m; k++) {
            if (k > 0) binom = binom * (double)(m - k + 1) / (double)k;
            double sgn = ((m - k) & 1) ? -1.0 : 1.0;
            qd[k] += d[m] * binom * pow(alpha, (double)k) * sgn;
        }
    }
    Poly p;
    for (int k = 0; k < K; k++) p.q[k] = (float)qd[k];
    return p;
}

extern "C" void kernel_launch(void* const* d_in, const int* in_sizes, int n_in,
                              void* d_out, int out_size) {
    const float* f1  = (const float*)d_in[0];
    const float* f2  = (const float*)d_in[1];
    const float* Wca = (const float*)d_in[2];
    const float* Wcv = (const float*)d_in[3];
    float* out = (float*)d_out;

    const int B = in_sizes[0] / 32;
    Poly p = make_tanh_poly();

    void* ctr = nullptr;
    cudaGetSymbolAddress(&ctr, g_ctr);
    cudaMemsetAsync(ctr, 0, 2 * sizeof(int));

    // kernel 1: 6 blocks/SM x 148 SMs, work stealing over ceil(B/32) batches
    cam_poly_kernel<<<888, 128>>>(f1, f2, Wca, Wcv, out, B, p);
    // kernel 2: exact overwrite of flagged (out-of-poly-range) samples
    cam_fix_kernel<<<148, 128>>>(f1, f2, Wca, Wcv, out, B);
}

// round 10
// speedup vs baseline: 2.9358x; 1.3089x over previous
#include <cuda_runtime.h>
#include <math.h>

// CAM_43344809951340 — factored-moment formulation (single kernel).
// out_a[i] = 0.1*relu( sum_j tanh(u_i v_j) Wca_j + u_i/RS ),  u,v = av*RS.
// tanh(x) ~ x * Q(x^2), deg-13 odd (KP=7 terms), fit on |x| <= 2.0
//  => sum_j tanh(u v_j) W_j = sum_k q_k u^(2k+1) M_k,  M_k = sum_j v_j^(2k+1) W_j.
// Per warp batch: 32 samples (lane = sample), smem-staged coalesced I/O.
// Samples with max|z| > 4.0 (~4e-3 of samples) are re-solved exactly INLINE
// by the whole warp (tanh.approx.f32 + shuffles) and overwritten.

#define RS   0.35355339059327379f   // sqrt(1/8)
#define IRS  2.8284271247461903f    // 1/RS
#define KP   7                      // poly terms (degree 13 odd)
#define VMAX 1.4142135623730951f    // 4.0 * RS : flag threshold on scaled v

struct Poly { float q[KP]; };

__device__ int g_ctr;               // batch counter

__device__ __forceinline__ float tanhfast(float x) {
    float y; asm("tanh.approx.f32 %0, %1;" : "=f"(y) : "f"(x));
    return y;
}

__global__ __launch_bounds__(128, 6)
void cam_poly_kernel(const float* __restrict__ f1, const float* __restrict__ f2,
                     const float* __restrict__ Wca, const float* __restrict__ Wcv,
                     float* __restrict__ out, int B, Poly pc)
{
    __shared__ float  rows[4][32 * 65];   // per-warp: 32 samples x 64 (stride 65)
    __shared__ float2 wsh[64];            // {Wca[j], Wcv[j]}

    const int tid = threadIdx.x;
    const int wrp = tid >> 5;
    const int l   = tid & 31;
    float* R = rows[wrp];

    if (tid < 64) wsh[tid] = make_float2(Wca[tid], Wcv[tid]);
    __syncthreads();

    float q[KP];
    #pragma unroll
    for (int k = 0; k < KP; k++) q[k] = 0.1f * pc.q[k];
    const float r01 = 0.1f * IRS;         // folded residual: 0.1 * u / RS

    // per-lane exact-path weights (for inline fixup)
    const float wca1 = Wca[l], wca2 = Wca[l + 32];
    const float wcv1 = Wcv[l], wcv2 = Wcv[l + 32];

    const int nbatch = (B + 31) >> 5;

    int batch = 0;
    if (l == 0) batch = atomicAdd(&g_ctr, 1);
    batch = __shfl_sync(0xffffffffu, batch, 0);

    while (batch < nbatch) {
        int nextb = 0;
        if (l == 0) nextb = atomicAdd(&g_ctr, 1);   // prefetch next id
        nextb = __shfl_sync(0xffffffffu, nextb, 0);

        const int base = batch << 5;

        // ---- stage: coalesced gmem -> smem, pre-scaled by RS ----
        #pragma unroll 4
        for (int c = 0; c < 32; c++) {
            int b = base + c;
            bool v = b < B;
            float x = v ? f1[b * 32 + l] : 0.0f;
            float y = v ? f2[b * 32 + l] : 0.0f;
            R[c * 65 + l]      = x * RS;
            R[c * 65 + 32 + l] = y * RS;
        }
        __syncwarp();

        // ---- phase 1: moments M_k = sum_j v_j^(2k+1) W_j (lane = sample) ----
        float Ma[KP], Mv[KP];
        #pragma unroll
        for (int k = 0; k < KP; k++) { Ma[k] = 0.0f; Mv[k] = 0.0f; }
        float mx = 0.0f;

        const float* myrow = &R[l * 65];
        #pragma unroll 8
        for (int j = 0; j < 64; j++) {
            float v = myrow[j];
            float2 w = wsh[j];
            mx = fmaxf(mx, fabsf(v));
            float w2 = v * v;
            float p = v;
            #pragma unroll
            for (int k = 0; k < KP; k++) {
                Ma[k] = fmaf(p, w.x, Ma[k]);
                Mv[k] = fmaf(p, w.y, Mv[k]);
                if (k < KP - 1) p *= w2;
            }
        }
        #pragma unroll
        for (int k = 0; k < KP; k++) { Ma[k] *= q[k]; Mv[k] *= q[k]; }

        // ---- phase 2: Horner per output, overwrite row in place ----
        #pragma unroll 8
        for (int i = 0; i < 32; i++) {
            float u = myrow[i];
            float w2 = u * u;
            float A = Ma[KP - 1];
            #pragma unroll
            for (int k = KP - 2; k >= 0; k--) A = fmaf(A, w2, Ma[k]);
            A += r01;
            ((float*)myrow)[i] = fmaxf(u * A, 0.0f);
        }
        #pragma unroll 8
        for (int i = 32; i < 64; i++) {
            float u = myrow[i];
            float w2 = u * u;
            float A = Mv[KP - 1];
            #pragma unroll
            for (int k = KP - 2; k >= 0; k--) A = fmaf(A, w2, Mv[k]);
            A += r01;
            ((float*)myrow)[i] = fmaxf(u * A, 0.0f);
        }
        __syncwarp();

        // ---- flush: coalesced smem -> gmem ----
        #pragma unroll 4
        for (int c = 0; c < 32; c++) {
            int b = base + c;
            if (b < B) {
                out[b * 64 + l]      = R[c * 65 + l];
                out[b * 64 + 32 + l] = R[c * 65 + 32 + l];
            }
        }

        // ---- inline exact fixup for out-of-range samples (rare: ~4e-3) ----
        unsigned fmask = __ballot_sync(0xffffffffu,
                                       (mx > VMAX) && ((base + l) < B));
        while (fmask) {
            int c = __ffs(fmask) - 1;
            fmask &= fmask - 1;
            int b = base + c;
            float z1 = f1[b * 32 + l];     // av[l]
            float z2 = f2[b * 32 + l];     // av[l+32]
            float acc_a = z1, acc_v = z2;
            #pragma unroll 4
            for (int j = 0; j < 32; j++) {
                float a1 = __shfl_sync(0xffffffffu, z1, j) * 0.125f;
                float a2 = __shfl_sync(0xffffffffu, z2, j) * 0.125f;
                float w1 = __shfl_sync(0xffffffffu, wca1, j);
                float w2 = __shfl_sync(0xffffffffu, wca2, j);
                float w3 = __shfl_sync(0xffffffffu, wcv1, j);
                float w4 = __shfl_sync(0xffffffffu, wcv2, j);
                acc_a = fmaf(tanhfast(z1 * a1), w1, acc_a);
                acc_a = fmaf(tanhfast(z1 * a2), w2, acc_a);
                acc_v = fmaf(tanhfast(z2 * a1), w3, acc_v);
                acc_v = fmaf(tanhfast(z2 * a2), w4, acc_v);
            }
            out[b * 64 + l]      = 0.1f * fmaxf(acc_a, 0.0f);
            out[b * 64 + 32 + l] = 0.1f * fmaxf(acc_v, 0.0f);
        }
        __syncwarp();

        batch = nextb;
    }
}

// ---- host: deg-13 odd Chebyshev fit of tanh on |x|<=2, double precision ----
static Poly make_tanh_poly(void)
{
    const int K = KP;
    const double W = 4.0;                 // w = x^2 in [0, 4]  (|x| <= 2)
    double g[KP], th[KP], c[KP];
    for (int i = 0; i < K; i++) {
        th[i] = M_PI * (2.0 * i + 1.0) / (2.0 * K);
        double zh = cos(th[i]);
        double w = 0.5 * W * (zh + 1.0);
        double x = sqrt(w);
        g[i] = tanh(x) / x;               // interior nodes: x > 0
    }
    for (int k = 0; k < K; k++) {
        double s = 0.0;
        for (int i = 0; i < K; i++) s += g[i] * cos(k * th[i]);
        c[k] = s * ((k == 0) ? 1.0 : 2.0) / K;
    }
    // Chebyshev(zh) -> monomial(zh)
    double d[KP + 1] = {0}, tp[KP + 1] = {0}, tc[KP + 1] = {0}, tn[KP + 1];
    tp[0] = 1.0;
    tc[1] = 1.0;
    d[0] += c[0];
    d[1] += c[1];
    for (int k = 2; k < K; k++) {
        for (int m = 0; m <= K; m++) tn[m] = -tp[m];
        for (int m = K; m >= 1; m--) tn[m] += 2.0 * tc[m - 1];
        for (int m = 0; m <= K; m++) { tp[m] = tc[m]; tc[m] = tn[m]; d[m] += c[k] * tc[m]; }
    }
    // zh = alpha*w - 1 -> monomials in raw w
    double alpha = 2.0 / W;
    double qd[KP] = {0};
    for (int m = 0; m < K; m++) {
        double binom = 1.0;
        for (int k = 0; k <= m; k++) {
            if (k > 0) binom = binom * (double)(m - k + 1) / (double)k;
            double sgn = ((m - k) & 1) ? -1.0 : 1.0;
            qd[k] += d[m] * binom * pow(alpha, (double)k) * sgn;
        }
    }
    Poly p;
    for (int k = 0; k < K; k++) p.q[k] = (float)qd[k];
    return p;
}

extern "C" void kernel_launch(void* const* d_in, const int* in_sizes, int n_in,
                              void* d_out, int out_size) {
    const float* f1  = (const float*)d_in[0];
    const float* f2  = (const float*)d_in[1];
    const float* Wca = (const float*)d_in[2];
    const float* Wcv = (const float*)d_in[3];
    float* out = (float*)d_out;

    const int B = in_sizes[0] / 32;
    Poly p = make_tanh_poly();

    void* ctr = nullptr;
    cudaGetSymbolAddress(&ctr, g_ctr);
    cudaMemsetAsync(ctr, 0, sizeof(int));

    // 6 blocks/SM x 148 SMs; work stealing over ceil(B/32) batches.
    cam_poly_kernel<<<888, 128>>>(f1, f2, Wca, Wcv, out, B, p);
}

// round 11
// speedup vs baseline: 3.0132x; 1.0263x over previous
#include <cuda_runtime.h>
#include <math.h>

// CAM_43344809951340 — factored-moment formulation, vectorized plumbing.
// tanh(s z_i z_j) = sum_k q_k s^(2k+1) z_i^(2k+1) z_j^(2k+1)  (deg-13 odd fit)
//  => row sum = sum_k q'_k z_i^(2k+1) M_k,  M_k = sum_j z_j^(2k+1) W_j,
// with q'_k = 0.1*q_k*s^(2k+1) folded on host. All f32 FMA; no MUFU.
// Lane = sample (32/warp-batch); smem staging with stride-68 rows so that
// float4 (LDS/STS.128) lane-major access AND scalar staged access are both
// bank-conflict-free. Weights live in __constant__ (LDCU, off the MIO pipe).
// Samples with max|z| > 4 (~4e-3) re-solved exactly inline with tanh.approx.

#define KP   7
#define ZMAX 4.0f

struct Poly { float q[KP]; };

__constant__ float cW[128];    // interleaved {Wca[j], Wcv[j]} j=0..63
__device__ int g_ctr;

__device__ __forceinline__ float tanhfast(float x) {
    float y; asm("tanh.approx.f32 %0, %1;" : "=f"(y) : "f"(x));
    return y;
}

__global__ __launch_bounds__(128, 6)
void cam_poly_kernel(const float* __restrict__ f1, const float* __restrict__ f2,
                     float* __restrict__ out, int B, Poly pc)
{
    __shared__ float rows[4][32 * 68];    // per-warp: 32 samples x 64 (stride 68)

    const int tid = threadIdx.x;
    const int wrp = tid >> 5;
    const int l   = tid & 31;
    float* R = rows[wrp];

    float q[KP];
    #pragma unroll
    for (int k = 0; k < KP; k++) q[k] = pc.q[k];   // pre-folded on host

    const int nbatch = (B + 31) >> 5;

    int batch = 0;
    if (l == 0) batch = atomicAdd(&g_ctr, 1);
    batch = __shfl_sync(0xffffffffu, batch, 0);

    while (batch < nbatch) {
        int nextb = 0;
        if (l == 0) nextb = atomicAdd(&g_ctr, 1);   // prefetch next id
        nextb = __shfl_sync(0xffffffffu, nextb, 0);

        const int base = batch << 5;
        const bool full = (base + 32 <= B);

        // ---- stage: raw float4 copy gmem -> smem (coalesced 512B/inst) ----
        if (full) {
            const float4* s1 = (const float4*)(f1 + (size_t)base * 32);
            const float4* s2 = (const float4*)(f2 + (size_t)base * 32);
            const int smp = (l >> 3), ft = (l & 7) * 4;
            #pragma unroll
            for (int c = 0; c < 8; c++)
                *(float4*)&R[(c * 4 + smp) * 68 + ft] = s1[c * 32 + l];
            #pragma unroll
            for (int c = 0; c < 8; c++)
                *(float4*)&R[(c * 4 + smp) * 68 + 32 + ft] = s2[c * 32 + l];
        } else {
            #pragma unroll 4
            for (int c = 0; c < 32; c++) {
                int b = base + c;
                bool v = b < B;
                R[c * 68 + l]      = v ? f1[b * 32 + l] : 0.0f;
                R[c * 68 + 32 + l] = v ? f2[b * 32 + l] : 0.0f;
            }
        }
        __syncwarp();

        // ---- phase 1: raw moments M_k = sum_j z_j^(2k+1) W_j (lane=sample) ----
        float Ma[KP], Mv[KP];
        #pragma unroll
        for (int k = 0; k < KP; k++) { Ma[k] = 0.0f; Mv[k] = 0.0f; }
        float mx = 0.0f;

        float* myrow = &R[l * 68];
        #pragma unroll
        for (int jq = 0; jq < 16; jq++) {
            float4 vv = *(const float4*)&myrow[jq * 4];
            const float2* wp = (const float2*)&cW[jq * 8];   // uniform -> LDCU
            #pragma unroll
            for (int e = 0; e < 4; e++) {
                float v = (&vv.x)[e];
                float2 w = wp[e];
                mx = fmaxf(mx, fabsf(v));
                float w2 = v * v;
                float p = v;
                #pragma unroll
                for (int k = 0; k < KP; k++) {
                    Ma[k] = fmaf(p, w.x, Ma[k]);
                    Mv[k] = fmaf(p, w.y, Mv[k]);
                    if (k < KP - 1) p *= w2;
                }
            }
        }
        #pragma unroll
        for (int k = 0; k < KP; k++) { Ma[k] *= q[k]; Mv[k] *= q[k]; }

        // ---- phase 2: Horner per output (float4), overwrite row ----
        #pragma unroll
        for (int iq = 0; iq < 8; iq++) {
            float4 u4 = *(const float4*)&myrow[iq * 4];
            #pragma unroll
            for (int e = 0; e < 4; e++) {
                float u = (&u4.x)[e];
                float w2 = u * u;
                float A = Ma[KP - 1];
                #pragma unroll
                for (int k = KP - 2; k >= 0; k--) A = fmaf(A, w2, Ma[k]);
                A += 0.1f;                        // folded residual 0.1*z
                (&u4.x)[e] = fmaxf(u * A, 0.0f);
            }
            *(float4*)&myrow[iq * 4] = u4;
        }
        #pragma unroll
        for (int iq = 8; iq < 16; iq++) {
            float4 u4 = *(const float4*)&myrow[iq * 4];
            #pragma unroll
            for (int e = 0; e < 4; e++) {
                float u = (&u4.x)[e];
                float w2 = u * u;
                float A = Mv[KP - 1];
                #pragma unroll
                for (int k = KP - 2; k >= 0; k--) A = fmaf(A, w2, Mv[k]);
                A += 0.1f;
                (&u4.x)[e] = fmaxf(u * A, 0.0f);
            }
            *(float4*)&myrow[iq * 4] = u4;
        }
        __syncwarp();

        // ---- flush: smem -> gmem, float4 coalesced ----
        if (full) {
            float4* o4 = (float4*)(out + (size_t)base * 64);
            #pragma unroll
            for (int c = 0; c < 16; c++) {
                int idx = c * 32 + l;
                o4[idx] = *(const float4*)&R[(idx >> 4) * 68 + (idx & 15) * 4];
            }
        } else {
            #pragma unroll 4
            for (int c = 0; c < 32; c++) {
                int b = base + c;
                if (b < B) {
                    out[b * 64 + l]      = R[c * 68 + l];
                    out[b * 64 + 32 + l] = R[c * 68 + 32 + l];
                }
            }
        }

        // ---- inline exact fixup for out-of-range samples (~4e-3) ----
        unsigned fmask = __ballot_sync(0xffffffffu,
                                       (mx > ZMAX) && ((base + l) < B));
        while (fmask) {
            int c = __ffs(fmask) - 1;
            fmask &= fmask - 1;
            int b = base + c;
            float z1 = f1[b * 32 + l];
            float z2 = f2[b * 32 + l];
            float wca1 = cW[2 * l], wcv1 = cW[2 * l + 1];
            float wca2 = cW[2 * (l + 32)], wcv2 = cW[2 * (l + 32) + 1];
            float acc_a = z1, acc_v = z2;
            #pragma unroll 4
            for (int j = 0; j < 32; j++) {
                float a1 = __shfl_sync(0xffffffffu, z1, j) * 0.125f;
                float a2 = __shfl_sync(0xffffffffu, z2, j) * 0.125f;
                float w1 = __shfl_sync(0xffffffffu, wca1, j);
                float w2 = __shfl_sync(0xffffffffu, wca2, j);
                float w3 = __shfl_sync(0xffffffffu, wcv1, j);
                float w4 = __shfl_sync(0xffffffffu, wcv2, j);
                acc_a = fmaf(tanhfast(z1 * a1), w1, acc_a);
                acc_a = fmaf(tanhfast(z1 * a2), w2, acc_a);
                acc_v = fmaf(tanhfast(z2 * a1), w3, acc_v);
                acc_v = fmaf(tanhfast(z2 * a2), w4, acc_v);
            }
            out[b * 64 + l]      = 0.1f * fmaxf(acc_a, 0.0f);
            out[b * 64 + 32 + l] = 0.1f * fmaxf(acc_v, 0.0f);
        }
        __syncwarp();

        batch = nextb;
    }
}

// ---- host: deg-13 odd Chebyshev fit of tanh on |x|<=2 (double precision),
//      with 0.1 output scale and s^(2k+1) (s = 1/8) folded into coefficients.
static Poly make_tanh_poly(void)
{
    const int K = KP;
    const double W = 4.0;                 // w = x^2 in [0, 4]
    double g[KP], th[KP], c[KP];
    for (int i = 0; i < K; i++) {
        th[i] = M_PI * (2.0 * i + 1.0) / (2.0 * K);
        double zh = cos(th[i]);
        double w = 0.5 * W * (zh + 1.0);
        double x = sqrt(w);
        g[i] = tanh(x) / x;
    }
    for (int k = 0; k < K; k++) {
        double s = 0.0;
        for (int i = 0; i < K; i++) s += g[i] * cos(k * th[i]);
        c[k] = s * ((k == 0) ? 1.0 : 2.0) / K;
    }
    double d[KP + 1] = {0}, tp[KP + 1] = {0}, tc[KP + 1] = {0}, tn[KP + 1];
    tp[0] = 1.0;
    tc[1] = 1.0;
    d[0] += c[0];
    d[1] += c[1];
    for (int k = 2; k < K; k++) {
        for (int m = 0; m <= K; m++) tn[m] = -tp[m];
        for (int m = K; m >= 1; m--) tn[m] += 2.0 * tc[m - 1];
        for (int m = 0; m <= K; m++) { tp[m] = tc[m]; tc[m] = tn[m]; d[m] += c[k] * tc[m]; }
    }
    double alpha = 2.0 / W;
    double qd[KP] = {0};
    for (int m = 0; m < K; m++) {
        double binom = 1.0;
        for (int k = 0; k <= m; k++) {
            if (k > 0) binom = binom * (double)(m - k + 1) / (double)k;
            double sgn = ((m - k) & 1) ? -1.0 : 1.0;
            qd[k] += d[m] * binom * pow(alpha, (double)k) * sgn;
        }
    }
    Poly p;
    for (int k = 0; k < K; k++) {
        double fold = 0.1 * pow(0.125, (double)(2 * k + 1));
        p.q[k] = (float)(qd[k] * fold);
    }
    return p;
}

extern "C" void kernel_launch(void* const* d_in, const int* in_sizes, int n_in,
                              void* d_out, int out_size) {
    const float* f1  = (const float*)d_in[0];
    const float* f2  = (const float*)d_in[1];
    const float* Wca = (const float*)d_in[2];
    const float* Wcv = (const float*)d_in[3];
    float* out = (float*)d_out;

    const int B = in_sizes[0] / 32;
    Poly p = make_tanh_poly();

    void* ctr = nullptr;
    cudaGetSymbolAddress(&ctr, g_ctr);
    cudaMemsetAsync(ctr, 0, sizeof(int));

    // Interleave {Wca[j], Wcv[j]} into __constant__ cW via strided D2D copies.
    void* cw = nullptr;
    cudaGetSymbolAddress(&cw, cW);
    cudaMemcpy2DAsync((char*)cw,     8, Wca, 4, 4, 64, cudaMemcpyDeviceToDevice);
    cudaMemcpy2DAsync((char*)cw + 4, 8, Wcv, 4, 4, 64, cudaMemcpyDeviceToDevice);

    // 6 blocks/SM x 148 SMs; work stealing over ceil(B/32) batches.
    cam_poly_kernel<<<888, 128>>>(f1, f2, out, B, p);
}

// round 12
// speedup vs baseline: 3.1249x; 1.0371x over previous
#include <cuda_runtime.h>
#include <math.h>

// CAM_43344809951340 — factored-moment formulation, thread-per-sample.
// tanh(s z_i z_j) = sum_k q_k s^(2k+1) z_i^(2k+1) z_j^(2k+1)  (deg-9 odd fit)
//  => row sum = sum_k q'_k z_i^(2k+1) M_k,  M_k = sum_j z_j^(2k+1) W_j,
// q'_k = 0.1*q_k*s^(2k+1) folded on host (double precision). All f32 FMA.
// Thread b owns sample b: 16 LDG.128 (own 128B rows, sector-exact), stream
// moments, re-read (L1 hit) for Horner, STG.128 direct. No smem, no atomics,
// no syncs. Samples with max|z| > 4 (~4e-3) fixed exactly by the warp inline.

#define KP   5
#define ZMAX 4.0f

struct Poly { float q[KP]; };

__constant__ float cW[128];    // interleaved {Wca[j], Wcv[j]} j=0..63

__device__ __forceinline__ float tanhfast(float x) {
    float y; asm("tanh.approx.f32 %0, %1;" : "=f"(y) : "f"(x));
    return y;
}

__global__ __launch_bounds__(128, 8)
void cam_poly_kernel(const float* __restrict__ f1, const float* __restrict__ f2,
                     float* __restrict__ out, int B, Poly pc)
{
    const int b  = blockIdx.x * 128 + threadIdx.x;
    const int bc = (b < B) ? b : (B - 1);          // clamped (keeps warp converged)

    const float4* r1 = (const float4*)(f1 + (size_t)bc * 32);
    const float4* r2 = (const float4*)(f2 + (size_t)bc * 32);
    const float2* w2c = (const float2*)cW;

    float q[KP];
    #pragma unroll
    for (int k = 0; k < KP; k++) q[k] = pc.q[k];   // pre-folded on host

    // ---- phase 1: raw moments M_k = sum_j z_j^(2k+1) W_j ----
    float Ma[KP], Mv[KP];
    #pragma unroll
    for (int k = 0; k < KP; k++) { Ma[k] = 0.0f; Mv[k] = 0.0f; }
    float mx = 0.0f;

    #pragma unroll
    for (int j4 = 0; j4 < 8; j4++) {
        float4 v4 = r1[j4];
        #pragma unroll
        for (int e = 0; e < 4; e++) {
            float v = (&v4.x)[e];
            float2 w = w2c[j4 * 4 + e];            // uniform -> const port
            mx = fmaxf(mx, fabsf(v));
            float vv = v * v;
            float p = v;
            #pragma unroll
            for (int k = 0; k < KP; k++) {
                Ma[k] = fmaf(p, w.x, Ma[k]);
                Mv[k] = fmaf(p, w.y, Mv[k]);
                if (k < KP - 1) p *= vv;
            }
        }
    }
    #pragma unroll
    for (int j4 = 0; j4 < 8; j4++) {
        float4 v4 = r2[j4];
        #pragma unroll
        for (int e = 0; e < 4; e++) {
            float v = (&v4.x)[e];
            float2 w = w2c[32 + j4 * 4 + e];
            mx = fmaxf(mx, fabsf(v));
            float vv = v * v;
            float p = v;
            #pragma unroll
            for (int k = 0; k < KP; k++) {
                Ma[k] = fmaf(p, w.x, Ma[k]);
                Mv[k] = fmaf(p, w.y, Mv[k]);
                if (k < KP - 1) p *= vv;
            }
        }
    }
    #pragma unroll
    for (int k = 0; k < KP; k++) { Ma[k] *= q[k]; Mv[k] *= q[k]; }

    // ---- phase 2: Horner per output, direct STG.128 ----
    float4* o4 = (float4*)(out + (size_t)bc * 64);
    const bool valid = (b < B);

    #pragma unroll
    for (int j4 = 0; j4 < 8; j4++) {
        float4 u4 = r1[j4];                        // L1 hit
        #pragma unroll
        for (int e = 0; e < 4; e++) {
            float u = (&u4.x)[e];
            float uu = u * u;
            float A = Ma[KP - 1];
            #pragma unroll
            for (int k = KP - 2; k >= 0; k--) A = fmaf(A, uu, Ma[k]);
            A += 0.1f;                             // folded residual 0.1*z
            (&u4.x)[e] = fmaxf(u * A, 0.0f);
        }
        if (valid) o4[j4] = u4;
    }
    #pragma unroll
    for (int j4 = 0; j4 < 8; j4++) {
        float4 u4 = r2[j4];                        // L1 hit
        #pragma unroll
        for (int e = 0; e < 4; e++) {
            float u = (&u4.x)[e];
            float uu = u * u;
            float A = Mv[KP - 1];
            #pragma unroll
            for (int k = KP - 2; k >= 0; k--) A = fmaf(A, uu, Mv[k]);
            A += 0.1f;
            (&u4.x)[e] = fmaxf(u * A, 0.0f);
        }
        if (valid) o4[8 + j4] = u4;
    }

    // ---- inline exact fixup for out-of-range samples (~4e-3 of samples) ----
    const int l = threadIdx.x & 31;
    unsigned fmask = __ballot_sync(0xffffffffu, (mx > ZMAX) && valid);
    if (fmask == 0) return;
    const float wca1 = cW[2 * l],        wcv1 = cW[2 * l + 1];
    const float wca2 = cW[2 * (l + 32)], wcv2 = cW[2 * (l + 32) + 1];
    while (fmask) {
        int c = __ffs(fmask) - 1;
        fmask &= fmask - 1;
        int bf = __shfl_sync(0xffffffffu, b, c);
        float z1 = f1[bf * 32 + l];
        float z2 = f2[bf * 32 + l];
        float acc_a = z1, acc_v = z2;
        #pragma unroll 4
        for (int j = 0; j < 32; j++) {
            float a1 = __shfl_sync(0xffffffffu, z1, j) * 0.125f;
            float a2 = __shfl_sync(0xffffffffu, z2, j) * 0.125f;
            float w1 = __shfl_sync(0xffffffffu, wca1, j);
            float w2 = __shfl_sync(0xffffffffu, wca2, j);
            float w3 = __shfl_sync(0xffffffffu, wcv1, j);
            float w4 = __shfl_sync(0xffffffffu, wcv2, j);
            acc_a = fmaf(tanhfast(z1 * a1), w1, acc_a);
            acc_a = fmaf(tanhfast(z1 * a2), w2, acc_a);
            acc_v = fmaf(tanhfast(z2 * a1), w3, acc_v);
            acc_v = fmaf(tanhfast(z2 * a2), w4, acc_v);
        }
        out[bf * 64 + l]      = 0.1f * fmaxf(acc_a, 0.0f);
        out[bf * 64 + 32 + l] = 0.1f * fmaxf(acc_v, 0.0f);
    }
}

// ---- host: deg-9 odd Chebyshev fit of tanh on |x|<=2 (double precision),
//      with 0.1 output scale and s^(2k+1) (s = 1/8) folded into coefficients.
static Poly make_tanh_poly(void)
{
    const int K = KP;
    const double W = 4.0;                 // w = x^2 in [0, 4]
    double g[KP], th[KP], c[KP];
    for (int i = 0; i < K; i++) {
        th[i] = M_PI * (2.0 * i + 1.0) / (2.0 * K);
        double zh = cos(th[i]);
        double w = 0.5 * W * (zh + 1.0);
        double x = sqrt(w);
        g[i] = tanh(x) / x;
    }
    for (int k = 0; k < K; k++) {
        double s = 0.0;
        for (int i = 0; i < K; i++) s += g[i] * cos(k * th[i]);
        c[k] = s * ((k == 0) ? 1.0 : 2.0) / K;
    }
    double d[KP + 1] = {0}, tp[KP + 1] = {0}, tc[KP + 1] = {0}, tn[KP + 1];
    tp[0] = 1.0;
    tc[1] = 1.0;
    d[0] += c[0];
    d[1] += c[1];
    for (int k = 2; k < K; k++) {
        for (int m = 0; m <= K; m++) tn[m] = -tp[m];
        for (int m = K; m >= 1; m--) tn[m] += 2.0 * tc[m - 1];
        for (int m = 0; m <= K; m++) { tp[m] = tc[m]; tc[m] = tn[m]; d[m] += c[k] * tc[m]; }
    }
    double alpha = 2.0 / W;
    double qd[KP] = {0};
    for (int m = 0; m < K; m++) {
        double binom = 1.0;
        for (int k = 0; k <= m; k++) {
            if (k > 0) binom = binom * (double)(m - k + 1) / (double)k;
            double sgn = ((m - k) & 1) ? -1.0 : 1.0;
            qd[k] += d[m] * binom * pow(alpha, (double)k) * sgn;
        }
    }
    Poly p;
    for (int k = 0; k < K; k++) {
        double fold = 0.1 * pow(0.125, (double)(2 * k + 1));
        p.q[k] = (float)(qd[k] * fold);
    }
    return p;
}

extern "C" void kernel_launch(void* const* d_in, const int* in_sizes, int n_in,
                              void* d_out, int out_size) {
    const float* f1  = (const float*)d_in[0];
    const float* f2  = (const float*)d_in[1];
    const float* Wca = (const float*)d_in[2];
    const float* Wcv = (const float*)d_in[3];
    float* out = (float*)d_out;

    const int B = in_sizes[0] / 32;
    Poly p = make_tanh_poly();

    // Interleave {Wca[j], Wcv[j]} into __constant__ cW via strided D2D copies.
    void* cw = nullptr;
    cudaGetSymbolAddress(&cw, cW);
    cudaMemcpy2DAsync((char*)cw,     8, Wca, 4, 4, 64, cudaMemcpyDeviceToDevice);
    cudaMemcpy2DAsync((char*)cw + 4, 8, Wcv, 4, 4, 64, cudaMemcpyDeviceToDevice);

    // Thread-per-sample, single wave: ceil(B/128) blocks.
    cam_poly_kernel<<<(B + 127) / 128, 128>>>(f1, f2, out, B, p);
}

// round 13
// speedup vs baseline: 4.8826x; 1.5625x over previous
#include <cuda_runtime.h>
#include <math.h>

// CAM_43344809951340 — factored-moment formulation, warp-transposed I/O.
// tanh(s z_i z_j) = sum_k q_k s^(2k+1) z_i^(2k+1) z_j^(2k+1)  (deg-9 odd fit)
//  => row sum = sum_k q'_k z_i^(2k+1) M_k,  M_k = sum_j z_j^(2k+1) W_j,
// q'_k = 0.1*q_k*s^(2k+1) folded on host (double). All f32 FMA, no MUFU.
// Warp owns 32 samples (lane = sample). Coalesced LDG.128 -> smem stride-68
// rows (conflict-free STS/LDS.128 both ways) -> per-lane row compute ->
// coalesced STG.128. ~160 L1 wavefronts/warp vs 1536 in the strided version.
// Samples with max|z| > 4 (~4e-3) re-solved exactly inline (tanh.approx.f32).

#define KP   5
#define ZMAX 4.0f
#define RSTR 68                   // smem row stride (floats): 64 data + 4 pad

struct Poly { float q[KP]; };

__constant__ float cW[128];       // interleaved {Wca[j], Wcv[j]} j=0..63

__device__ __forceinline__ float tanhfast(float x) {
    float y; asm("tanh.approx.f32 %0, %1;" : "=f"(y) : "f"(x));
    return y;
}

__global__ __launch_bounds__(128, 6)
void cam_poly_kernel(const float* __restrict__ f1, const float* __restrict__ f2,
                     float* __restrict__ out, int B, Poly pc)
{
    __shared__ float rows[4][32 * RSTR];

    const int tid  = threadIdx.x;
    const int wrp  = tid >> 5;
    const int l    = tid & 31;
    const int wbase = blockIdx.x * 128 + wrp * 32;
    if (wbase >= B) return;
    float* R = rows[wrp];

    float q[KP];
    #pragma unroll
    for (int k = 0; k < KP; k++) q[k] = pc.q[k];   // pre-folded on host

    const bool full = (wbase + 32 <= B);

    // ---- stage: coalesced LDG.128 -> smem rows (transpose) ----
    if (full) {
        const float4* s1 = (const float4*)(f1 + (size_t)wbase * 32);
        const float4* s2 = (const float4*)(f2 + (size_t)wbase * 32);
        const int smp = l >> 3, ft = (l & 7) * 4;
        #pragma unroll
        for (int c = 0; c < 8; c++)
            *(float4*)&R[(c * 4 + smp) * RSTR + ft] = s1[c * 32 + l];
        #pragma unroll
        for (int c = 0; c < 8; c++)
            *(float4*)&R[(c * 4 + smp) * RSTR + 32 + ft] = s2[c * 32 + l];
    } else {
        #pragma unroll 4
        for (int c = 0; c < 32; c++) {
            int b = wbase + c;
            bool v = b < B;
            R[c * RSTR + l]      = v ? f1[b * 32 + l] : 0.0f;
            R[c * RSTR + 32 + l] = v ? f2[b * 32 + l] : 0.0f;
        }
    }
    __syncwarp();

    // ---- phase 1: raw moments M_k = sum_j z_j^(2k+1) W_j (lane = sample) ----
    float Ma[KP], Mv[KP];
    #pragma unroll
    for (int k = 0; k < KP; k++) { Ma[k] = 0.0f; Mv[k] = 0.0f; }
    float mx = 0.0f;

    float* myrow = &R[l * RSTR];
    const float2* w2c = (const float2*)cW;
    #pragma unroll
    for (int jq = 0; jq < 16; jq++) {
        float4 v4 = *(const float4*)&myrow[jq * 4];
        #pragma unroll
        for (int e = 0; e < 4; e++) {
            float v = (&v4.x)[e];
            float2 w = w2c[jq * 4 + e];            // uniform -> const port
            mx = fmaxf(mx, fabsf(v));
            float vv = v * v;
            float p = v;
            #pragma unroll
            for (int k = 0; k < KP; k++) {
                Ma[k] = fmaf(p, w.x, Ma[k]);
                Mv[k] = fmaf(p, w.y, Mv[k]);
                if (k < KP - 1) p *= vv;
            }
        }
    }
    #pragma unroll
    for (int k = 0; k < KP; k++) { Ma[k] *= q[k]; Mv[k] *= q[k]; }

    // ---- phase 2: Horner per output, write back into own row ----
    #pragma unroll
    for (int jq = 0; jq < 8; jq++) {
        float4 u4 = *(const float4*)&myrow[jq * 4];
        #pragma unroll
        for (int e = 0; e < 4; e++) {
            float u = (&u4.x)[e];
            float uu = u * u;
            float A = Ma[KP - 1];
            #pragma unroll
            for (int k = KP - 2; k >= 0; k--) A = fmaf(A, uu, Ma[k]);
            A += 0.1f;                             // folded residual 0.1*z
            (&u4.x)[e] = fmaxf(u * A, 0.0f);
        }
        *(float4*)&myrow[jq * 4] = u4;
    }
    #pragma unroll
    for (int jq = 8; jq < 16; jq++) {
        float4 u4 = *(const float4*)&myrow[jq * 4];
        #pragma unroll
        for (int e = 0; e < 4; e++) {
            float u = (&u4.x)[e];
            float uu = u * u;
            float A = Mv[KP - 1];
            #pragma unroll
            for (int k = KP - 2; k >= 0; k--) A = fmaf(A, uu, Mv[k]);
            A += 0.1f;
            (&u4.x)[e] = fmaxf(u * A, 0.0f);
        }
        *(float4*)&myrow[jq * 4] = u4;
    }
    __syncwarp();

    // ---- flush: smem rows -> coalesced STG.128 ----
    if (full) {
        float4* o4 = (float4*)(out + (size_t)wbase * 64);
        #pragma unroll
        for (int c = 0; c < 16; c++) {
            int g = c * 32 + l;                    // global float4 index
            o4[g] = *(const float4*)&R[(g >> 4) * RSTR + (g & 15) * 4];
        }
    } else {
        #pragma unroll 4
        for (int c = 0; c < 32; c++) {
            int b = wbase + c;
            if (b < B) {
                out[b * 64 + l]      = R[c * RSTR + l];
                out[b * 64 + 32 + l] = R[c * RSTR + 32 + l];
            }
        }
    }

    // ---- inline exact fixup for out-of-range samples (~4e-3 of samples) ----
    const bool valid = (wbase + l) < B;
    unsigned fmask = __ballot_sync(0xffffffffu, (mx > ZMAX) && valid);
    if (fmask == 0) return;
    const float wca1 = cW[2 * l],        wcv1 = cW[2 * l + 1];
    const float wca2 = cW[2 * (l + 32)], wcv2 = cW[2 * (l + 32) + 1];
    while (fmask) {
        int c = __ffs(fmask) - 1;
        fmask &= fmask - 1;
        int bf = wbase + c;
        float z1 = f1[bf * 32 + l];
        float z2 = f2[bf * 32 + l];
        float acc_a = z1, acc_v = z2;
        #pragma unroll 4
        for (int j = 0; j < 32; j++) {
            float a1 = __shfl_sync(0xffffffffu, z1, j) * 0.125f;
            float a2 = __shfl_sync(0xffffffffu, z2, j) * 0.125f;
            float w1 = __shfl_sync(0xffffffffu, wca1, j);
            float w2 = __shfl_sync(0xffffffffu, wca2, j);
            float w3 = __shfl_sync(0xffffffffu, wcv1, j);
            float w4 = __shfl_sync(0xffffffffu, wcv2, j);
            acc_a = fmaf(tanhfast(z1 * a1), w1, acc_a);
            acc_a = fmaf(tanhfast(z1 * a2), w2, acc_a);
            acc_v = fmaf(tanhfast(z2 * a1), w3, acc_v);
            acc_v = fmaf(tanhfast(z2 * a2), w4, acc_v);
        }
        out[bf * 64 + l]      = 0.1f * fmaxf(acc_a, 0.0f);
        out[bf * 64 + 32 + l] = 0.1f * fmaxf(acc_v, 0.0f);
    }
}

// ---- host: deg-9 odd Chebyshev fit of tanh on |x|<=2 (double precision),
//      with 0.1 output scale and s^(2k+1) (s = 1/8) folded into coefficients.
static Poly make_tanh_poly(void)
{
    const int K = KP;
    const double W = 4.0;                 // w = x^2 in [0, 4]
    double g[KP], th[KP], c[KP];
    for (int i = 0; i < K; i++) {
        th[i] = M_PI * (2.0 * i + 1.0) / (2.0 * K);
        double zh = cos(th[i]);
        double w = 0.5 * W * (zh + 1.0);
        double x = sqrt(w);
        g[i] = tanh(x) / x;
    }
    for (int k = 0; k < K; k++) {
        double s = 0.0;
        for (int i = 0; i < K; i++) s += g[i] * cos(k * th[i]);
        c[k] = s * ((k == 0) ? 1.0 : 2.0) / K;
    }
    double d[KP + 1] = {0}, tp[KP + 1] = {0}, tc[KP + 1] = {0}, tn[KP + 1];
    tp[0] = 1.0;
    tc[1] = 1.0;
    d[0] += c[0];
    d[1] += c[1];
    for (int k = 2; k < K; k++) {
        for (int m = 0; m <= K; m++) tn[m] = -tp[m];
        for (int m = K; m >= 1; m--) tn[m] += 2.0 * tc[m - 1];
        for (int m = 0; m <= K; m++) { tp[m] = tc[m]; tc[m] = tn[m]; d[m] += c[k] * tc[m]; }
    }
    double alpha = 2.0 / W;
    double qd[KP] = {0};
    for (int m = 0; m < K; m++) {
        double binom = 1.0;
        for (int k = 0; k <= m; k++) {
            if (k > 0) binom = binom * (double)(m - k + 1) / (double)k;
            double sgn = ((m - k) & 1) ? -1.0 : 1.0;
            qd[k] += d[m] * binom * pow(alpha, (double)k) * sgn;
        }
    }
    Poly p;
    for (int k = 0; k < KP; k++) {
        double fold = 0.1 * pow(0.125, (double)(2 * k + 1));
        p.q[k] = (float)(qd[k] * fold);
    }
    return p;
}

extern "C" void kernel_launch(void* const* d_in, const int* in_sizes, int n_in,
                              void* d_out, int out_size) {
    const float* f1  = (const float*)d_in[0];
    const float* f2  = (const float*)d_in[1];
    const float* Wca = (const float*)d_in[2];
    const float* Wcv = (const float*)d_in[3];
    float* out = (float*)d_out;

    const int B = in_sizes[0] / 32;
    Poly p = make_tanh_poly();

    // Interleave {Wca[j], Wcv[j]} into __constant__ cW via strided D2D copies.
    void* cw = nullptr;
    cudaGetSymbolAddress(&cw, cW);
    cudaMemcpy2DAsync((char*)cw,     8, Wca, 4, 4, 64, cudaMemcpyDeviceToDevice);
    cudaMemcpy2DAsync((char*)cw + 4, 8, Wcv, 4, 4, 64, cudaMemcpyDeviceToDevice);

    // 128 samples per block (32 per warp), single wave.
    cam_poly_kernel<<<(B + 127) / 128, 128>>>(f1, f2, out, B, p);
}